// round 15
// baseline (speedup 1.0000x reference)
#include <cuda_runtime.h>
#include <cuda_fp16.h>
#include <cstdint>
#include <cstddef>

#define N_NODES 100000
#define N_EDGES 1600000
#define N_GRAPHS 4096
#define HID 512
#define M_PAD 100096            // 782 * 128
#define NCHUNK ((N_NODES + 1023) / 1024)

// ---------------- scratch (device globals; allocation-free) ----------------
__device__ uint16_t g_hh[(size_t)M_PAD * HID];   // node features (half)
__device__ uint16_t g_th[(size_t)M_PAD * HID];   // agg output (half)
__device__ uint16_t g_mh[(size_t)M_PAD * HID];   // MLP hidden (half)
__device__ uint16_t g_poolh[(size_t)N_GRAPHS * HID];
__device__ float    g_p1[(size_t)N_GRAPHS * 256];
__device__ uint16_t g_wh[5 * 512 * 512 + 256 * 512];  // [N,K] half weights
// CSR scratch
__device__ int g_deg[N_NODES];
__device__ int g_rows[N_NODES + 1];
__device__ int g_cur[N_NODES];
__device__ int g_csr[N_EDGES];
__device__ int g_gstart[N_GRAPHS + 1];
__device__ int g_bsum[NCHUNK];

__device__ __forceinline__ uint16_t f2h(float x) {
    return __half_as_ushort(__float2half_rn(x));
}

// ---------------- CSR build ----------------
__global__ void deg_count(const int* __restrict__ dst) {
    int e = blockIdx.x * blockDim.x + threadIdx.x;
    if (e < N_EDGES) atomicAdd(&g_deg[dst[e]], 1);
}

__global__ __launch_bounds__(1024) void scan1() {
    __shared__ int s[1024];
    const int b = blockIdx.x;
    const int tid = threadIdx.x;
    const int i = b * 1024 + tid;
    int v = (i < N_NODES) ? g_deg[i] : 0;
    s[tid] = v;
    __syncthreads();
#pragma unroll
    for (int off = 1; off < 1024; off <<= 1) {
        int t = (tid >= off) ? s[tid - off] : 0;
        __syncthreads();
        s[tid] += t;
        __syncthreads();
    }
    if (i < N_NODES) g_rows[i] = s[tid] - v;
    if (tid == 1023) g_bsum[b] = s[1023];
}

// scan3 with fused carry + fused graph_ranges (batch is sorted ascending)
__global__ __launch_bounds__(1024) void scan3(const int* __restrict__ batch) {
    __shared__ int carry;
    const int b = blockIdx.x;
    if (threadIdx.x == 0) {
        int c = 0;
        for (int i = 0; i < b; i++) c += g_bsum[i];
        carry = c;
        if (b == NCHUNK - 1) g_rows[N_NODES] = c + g_bsum[b];
    }
    __syncthreads();
    const int i = b * 1024 + threadIdx.x;
    if (i < N_NODES) {
        int r = g_rows[i] + carry;
        g_rows[i] = r;
        g_cur[i] = r;
    }
    // fused graph_ranges: global ids 0..N_GRAPHS do a lower_bound on batch
    if (i <= N_GRAPHS) {
        if (i == N_GRAPHS) {
            g_gstart[i] = N_NODES;
        } else {
            int lo = 0, hi = N_NODES;
            while (lo < hi) {
                int mid = (lo + hi) >> 1;
                if (batch[mid] < i) lo = mid + 1; else hi = mid;
            }
            g_gstart[i] = lo;
        }
    }
}

__global__ void csr_scatter(const int* __restrict__ src, const int* __restrict__ dst) {
    int e = blockIdx.x * blockDim.x + threadIdx.x;
    if (e >= N_EDGES) return;
    int pos = atomicAdd(&g_cur[dst[e]], 1);
    g_csr[pos] = src[e];
}

// ---------------- fused layer-1: agg7 + MLP-in ----------------
__global__ __launch_bounds__(256) void agg_mlp7(const float* __restrict__ x,
                                                const float* __restrict__ w,
                                                const float* __restrict__ bias) {
    __shared__ float sw[7 * 512];
    __shared__ float sb[512];
    for (int i = threadIdx.x; i < 7 * 512; i += 256) sw[i] = w[i];
    for (int i = threadIdx.x; i < 512; i += 256) sb[i] = bias[i];
    __syncthreads();

    const int lane = threadIdx.x & 31;
    const int wid = threadIdx.x >> 5;

    for (int node = blockIdx.x * 8 + wid; node < N_NODES; node += gridDim.x * 8) {
        int beg = g_rows[node], end = g_rows[node + 1];
        float a[7];
#pragma unroll
        for (int k = 0; k < 7; k++) a[k] = (lane == 0) ? x[(size_t)node * 7 + k] : 0.f;
        for (int e = beg + lane; e < end; e += 32) {
            int s = g_csr[e];
#pragma unroll
            for (int k = 0; k < 7; k++) a[k] += x[(size_t)s * 7 + k];
        }
#pragma unroll
        for (int off = 16; off; off >>= 1)
#pragma unroll
            for (int k = 0; k < 7; k++) a[k] += __shfl_xor_sync(0xFFFFFFFF, a[k], off);

        uint16_t* orow = g_mh + (size_t)node * 512;
#pragma unroll
        for (int jj = 0; jj < 16; jj++) {
            int j = jj * 32 + lane;
            float acc = sb[j];
#pragma unroll
            for (int k = 0; k < 7; k++) acc = fmaf(a[k], sw[k * 512 + j], acc);
            orow[j] = f2h(fmaxf(acc, 0.f));
        }
    }
}

// ---------------- L2-blocked aggregation (half in/out, fp32 sums) ----------------
// Streaming (__stcs) output stores keep the 51 MB gather working set L2-resident.
__global__ __launch_bounds__(256) void csr_aggh_chunk() {
    int w = (int)(((long long)blockIdx.x * blockDim.x + threadIdx.x) >> 5);
    int lane = threadIdx.x & 31;
    if (w >= N_NODES) return;
    const int off = blockIdx.y * 256 + lane * 8;  // halves
    const int beg = g_rows[w], end = g_rows[w + 1];
    const uint16_t* base = g_hh + off;

    float acc[8];
    {
        uint4 s = *(const uint4*)(base + (size_t)w * HID);
        const __half2* p = (const __half2*)&s;
#pragma unroll
        for (int q = 0; q < 4; q++) {
            float2 f = __half22float2(p[q]);
            acc[q * 2] = f.x; acc[q * 2 + 1] = f.y;
        }
    }

    int e = beg;
    for (; e + 4 <= end; e += 4) {
        int s0 = g_csr[e], s1 = g_csr[e + 1], s2 = g_csr[e + 2], s3 = g_csr[e + 3];
        uint4 v0 = *(const uint4*)(base + (size_t)s0 * HID);
        uint4 v1 = *(const uint4*)(base + (size_t)s1 * HID);
        uint4 v2 = *(const uint4*)(base + (size_t)s2 * HID);
        uint4 v3 = *(const uint4*)(base + (size_t)s3 * HID);
        const __half2* p0 = (const __half2*)&v0;
        const __half2* p1 = (const __half2*)&v1;
        const __half2* p2 = (const __half2*)&v2;
        const __half2* p3 = (const __half2*)&v3;
#pragma unroll
        for (int q = 0; q < 4; q++) {
            float2 f0 = __half22float2(p0[q]);
            float2 f1 = __half22float2(p1[q]);
            float2 f2 = __half22float2(p2[q]);
            float2 f3 = __half22float2(p3[q]);
            acc[q * 2]     += (f0.x + f1.x) + (f2.x + f3.x);
            acc[q * 2 + 1] += (f0.y + f1.y) + (f2.y + f3.y);
        }
    }
    for (; e < end; e++) {
        uint4 v0 = *(const uint4*)(base + (size_t)g_csr[e] * HID);
        const __half2* p0 = (const __half2*)&v0;
#pragma unroll
        for (int q = 0; q < 4; q++) {
            float2 f0 = __half22float2(p0[q]);
            acc[q * 2] += f0.x;
            acc[q * 2 + 1] += f0.y;
        }
    }

    uint4 o;
    __half2* po = (__half2*)&o;
#pragma unroll
    for (int q = 0; q < 4; q++)
        po[q] = __floats2half2_rn(acc[q * 2], acc[q * 2 + 1]);
    __stcs((uint4*)(g_th + (size_t)w * HID + off), o);
}

// ---------------- all weight transposes fused: [K,N] fp32 -> [N,K] half ----------------
// Regions 0..4: 512x512 (256 tiles each). Region 5: K=512,N=256 (128 tiles).
__global__ void w_to_half_all(const float* __restrict__ w0, const float* __restrict__ w1,
                              const float* __restrict__ w2, const float* __restrict__ w3,
                              const float* __restrict__ w4, const float* __restrict__ w5) {
    __shared__ float t[32][33];
    const int bx = blockIdx.x;
    const float* in;
    uint16_t* outp;
    int N, tile;
    if (bx < 1280) {
        int region = bx >> 8;
        tile = bx & 255;
        N = 512;
        switch (region) {
            case 0: in = w0; break;
            case 1: in = w1; break;
            case 2: in = w2; break;
            case 3: in = w3; break;
            default: in = w4; break;
        }
        outp = g_wh + (size_t)region * 262144;
    } else {
        tile = bx - 1280;
        N = 256;
        in = w5;
        outp = g_wh + (size_t)5 * 262144;
    }
    const int ntiles_n = N >> 5;
    const int n0 = (tile % ntiles_n) * 32;
    const int k0 = (tile / ntiles_n) * 32;
    const int K = 512;

    int tx = threadIdx.x, ty = threadIdx.y;  // (32,8)
#pragma unroll
    for (int i = 0; i < 4; i++)
        t[ty + i * 8][tx] = in[(size_t)(k0 + ty + i * 8) * N + n0 + tx];
    __syncthreads();
#pragma unroll
    for (int i = 0; i < 4; i++)
        outp[(size_t)(n0 + ty + i * 8) * K + k0 + tx] = f2h(t[tx][ty + i * 8]);
}

// ---------------- FP16 mma GEMM, 2-stage cp.async, 2 CTAs/SM (R12 best config) ----------------
#define STGH_BYTES 32768
#define GHSM_BYTES (2 * STGH_BYTES)

__device__ __forceinline__ void cp16(uint32_t dst, const void* src) {
    asm volatile("cp.async.cg.shared.global [%0], [%1], 16;" :: "r"(dst), "l"(src));
}

__device__ __forceinline__ void ldsm4(uint32_t* r, uint32_t a) {
    asm volatile("ldmatrix.sync.aligned.m8n8.x4.shared.b16 {%0,%1,%2,%3}, [%4];"
                 : "=r"(r[0]), "=r"(r[1]), "=r"(r[2]), "=r"(r[3]) : "r"(a));
}
__device__ __forceinline__ void ldsm2(uint32_t* r, uint32_t a) {
    asm volatile("ldmatrix.sync.aligned.m8n8.x2.shared.b16 {%0,%1}, [%2];"
                 : "=r"(r[0]), "=r"(r[1]) : "r"(a));
}

__device__ __forceinline__ void mma_h(float* d, const uint32_t* a, const uint32_t* b) {
    asm volatile(
        "mma.sync.aligned.m16n8k16.row.col.f32.f16.f16.f32 "
        "{%0,%1,%2,%3},{%4,%5,%6,%7},{%8,%9},{%0,%1,%2,%3};\n"
        : "+f"(d[0]), "+f"(d[1]), "+f"(d[2]), "+f"(d[3])
        : "r"(a[0]), "r"(a[1]), "r"(a[2]), "r"(a[3]), "r"(b[0]), "r"(b[1]));
}

// OUT_F32: store float2 to C (fp32, ldc); else half2 to C (half, ldc).
template <bool OUT_F32>
__global__ __launch_bounds__(256, 2) void gemm_h(
    int M, int ldc,
    const uint16_t* __restrict__ A, const uint16_t* __restrict__ B,
    const float* __restrict__ bias, void* __restrict__ Cv) {
    extern __shared__ __align__(128) char smc[];
    uint32_t smem_u32;
    asm("{ .reg .u64 t; cvta.to.shared.u64 t, %1; cvt.u32.u64 %0, t; }"
        : "=r"(smem_u32) : "l"(smc));

    const int tid = threadIdx.x;
    const int lane = tid & 31;
    const int warp = tid >> 5;
    const int wy = warp & 1;   // m 0/64
    const int wx = warp >> 1;  // n 0/32/64/96
    const int m0 = blockIdx.y * 128;
    const int n0 = blockIdx.x * 128;

    const int cr = tid >> 1;
    const int cb = (tid & 1) * 4;

    auto issue = [&](int ks) {
        uint32_t sa = smem_u32 + (uint32_t)(ks & 1) * STGH_BYTES;
        uint32_t sb = sa + 16384;
        const uint16_t* Ar = A + (size_t)(m0 + cr) * 512 + ks * 64;
        const uint16_t* Br = B + (size_t)(n0 + cr) * 512 + ks * 64;
#pragma unroll
        for (int q = 0; q < 4; q++) {
            int ch = cb + q;
            int sch = ch ^ (cr & 7);
            cp16(sa + (uint32_t)(cr * 128 + sch * 16), Ar + ch * 8);
            cp16(sb + (uint32_t)(cr * 128 + sch * 16), Br + ch * 8);
        }
        asm volatile("cp.async.commit_group;");
    };

    issue(0);

    float acc[4][4][4];
#pragma unroll
    for (int i = 0; i < 4; i++)
#pragma unroll
        for (int j = 0; j < 4; j++)
#pragma unroll
            for (int r = 0; r < 4; r++) acc[i][j][r] = 0.f;

    const int arow = lane & 15;
    const int asel = lane >> 4;
    const int brow = lane & 7;
    const int bsel = (lane >> 3) & 1;

    const int nks = 8;  // 512/64
    for (int ks = 0; ks < nks; ks++) {
        if (ks + 1 < nks) issue(ks + 1);
        else asm volatile("cp.async.commit_group;");
        asm volatile("cp.async.wait_group %0;" :: "n"(1));
        __syncthreads();

        uint32_t sa = smem_u32 + (uint32_t)(ks & 1) * STGH_BYTES;
        uint32_t sb = sa + 16384;
#pragma unroll
        for (int kk = 0; kk < 4; kk++) {
            uint32_t af[4][4], bf[4][2];
            const int ach = (2 * kk + asel) ^ (arow & 7);
            const int bch = (2 * kk + bsel) ^ brow;
#pragma unroll
            for (int i = 0; i < 4; i++)
                ldsm4(af[i], sa + (uint32_t)((wy * 64 + i * 16 + arow) * 128 + ach * 16));
#pragma unroll
            for (int j = 0; j < 4; j++)
                ldsm2(bf[j], sb + (uint32_t)((wx * 32 + j * 8 + brow) * 128 + bch * 16));
#pragma unroll
            for (int i = 0; i < 4; i++)
#pragma unroll
                for (int j = 0; j < 4; j++) mma_h(acc[i][j], af[i], bf[j]);
        }
        __syncthreads();
    }

    const int crow = lane >> 2;
    const int ccol = (lane & 3) << 1;
#pragma unroll
    for (int i = 0; i < 4; i++) {
        int r0 = m0 + wy * 64 + i * 16 + crow;
        int r1 = r0 + 8;
#pragma unroll
        for (int j = 0; j < 4; j++) {
            int c = n0 + wx * 32 + j * 8 + ccol;
            float b0 = bias[c], b1 = bias[c + 1];
            float v00 = fmaxf(acc[i][j][0] + b0, 0.f);
            float v01 = fmaxf(acc[i][j][1] + b1, 0.f);
            float v10 = fmaxf(acc[i][j][2] + b0, 0.f);
            float v11 = fmaxf(acc[i][j][3] + b1, 0.f);
            if (OUT_F32) {
                float* C = (float*)Cv;
                if (r0 < M) { float2 v = {v00, v01}; *(float2*)&C[(size_t)r0 * ldc + c] = v; }
                if (r1 < M) { float2 v = {v10, v11}; *(float2*)&C[(size_t)r1 * ldc + c] = v; }
            } else {
                uint16_t* C = (uint16_t*)Cv;
                if (r0 < M) {
                    __half2 v = __floats2half2_rn(v00, v01);
                    *(uint32_t*)&C[(size_t)r0 * ldc + c] = *(uint32_t*)&v;
                }
                if (r1 < M) {
                    __half2 v = __floats2half2_rn(v10, v11);
                    *(uint32_t*)&C[(size_t)r1 * ldc + c] = *(uint32_t*)&v;
                }
            }
        }
    }
}

// ---------------- pooling + head ----------------
__global__ __launch_bounds__(128) void pool_mean() {
    int g = blockIdx.x;
    int beg = g_gstart[g], end = g_gstart[g + 1];
    const int t = threadIdx.x;  // 4 halves each
    float a0 = 0.f, a1 = 0.f, a2 = 0.f, a3 = 0.f;
    for (int n = beg; n < end; n++) {
        uint2 v = *(const uint2*)(g_hh + (size_t)n * HID + t * 4);
        float2 f0 = __half22float2(*(__half2*)&v.x);
        float2 f1 = __half22float2(*(__half2*)&v.y);
        a0 += f0.x; a1 += f0.y; a2 += f1.x; a3 += f1.y;
    }
    float c = fmaxf((float)(end - beg), 1.f);
    uint2 o;
    __half2 o0 = __floats2half2_rn(a0 / c, a1 / c);
    __half2 o1 = __floats2half2_rn(a2 / c, a3 / c);
    o.x = *(uint32_t*)&o0; o.y = *(uint32_t*)&o1;
    *(uint2*)(g_poolh + (size_t)g * HID + t * 4) = o;
}

__global__ void head2(const float* __restrict__ w, const float* __restrict__ b,
                      float* __restrict__ out) {
    int g = blockIdx.x;
    int o = threadIdx.x;
    if (o >= 12) return;
    float acc = b[o];
    const float* row = g_p1 + (size_t)g * 256;
#pragma unroll 8
    for (int k = 0; k < 256; k++) acc = fmaf(row[k], w[k * 12 + o], acc);
    out[(size_t)g * 12 + o] = acc;
}

// ---------------- launch ----------------
extern "C" void kernel_launch(void* const* d_in, const int* in_sizes, int n_in,
                              void* d_out, int out_size) {
    const float* x = (const float*)d_in[0];
    const int* ei = (const int*)d_in[1];
    const int* src = ei;
    const int* dst = ei + N_EDGES;
    const int* batch = (const int*)d_in[2];
    const float* c1w1 = (const float*)d_in[3];
    const float* c1b1 = (const float*)d_in[4];
    const float* c1w2 = (const float*)d_in[5];
    const float* c1b2 = (const float*)d_in[6];
    const float* c2w1 = (const float*)d_in[7];
    const float* c2b1 = (const float*)d_in[8];
    const float* c2w2 = (const float*)d_in[9];
    const float* c2b2 = (const float*)d_in[10];
    const float* c3w1 = (const float*)d_in[11];
    const float* c3b1 = (const float*)d_in[12];
    const float* c3w2 = (const float*)d_in[13];
    const float* c3b2 = (const float*)d_in[14];
    const float* lw1 = (const float*)d_in[15];
    const float* lb1 = (const float*)d_in[16];
    const float* lw2 = (const float*)d_in[17];
    const float* lb2 = (const float*)d_in[18];
    float* out = (float*)d_out;

    uint16_t *p_hh, *p_th, *p_mh, *p_poolh, *p_wh;
    float *p_p1;
    int *p_deg;
    cudaGetSymbolAddress((void**)&p_hh, g_hh);
    cudaGetSymbolAddress((void**)&p_th, g_th);
    cudaGetSymbolAddress((void**)&p_mh, g_mh);
    cudaGetSymbolAddress((void**)&p_poolh, g_poolh);
    cudaGetSymbolAddress((void**)&p_wh, g_wh);
    cudaGetSymbolAddress((void**)&p_p1, g_p1);
    cudaGetSymbolAddress((void**)&p_deg, g_deg);

    uint16_t* h_c1w2 = p_wh + 0 * 262144;
    uint16_t* h_c2w1 = p_wh + 1 * 262144;
    uint16_t* h_c2w2 = p_wh + 2 * 262144;
    uint16_t* h_c3w1 = p_wh + 3 * 262144;
    uint16_t* h_c3w2 = p_wh + 4 * 262144;
    uint16_t* h_lw1  = p_wh + 5 * 262144;

    cudaFuncSetAttribute(gemm_h<true>, cudaFuncAttributeMaxDynamicSharedMemorySize, GHSM_BYTES);
    cudaFuncSetAttribute(gemm_h<false>, cudaFuncAttributeMaxDynamicSharedMemorySize, GHSM_BYTES);

    // ---- CSR build + graph ranges + weight prep ----
    cudaMemsetAsync(p_deg, 0, N_NODES * sizeof(int));
    deg_count<<<(N_EDGES + 255) / 256, 256>>>(dst);
    scan1<<<NCHUNK, 1024>>>();
    scan3<<<NCHUNK, 1024>>>(batch);
    csr_scatter<<<(N_EDGES + 255) / 256, 256>>>(src, dst);
    w_to_half_all<<<1408, dim3(32, 8)>>>(c1w2, c2w1, c2w2, c3w1, c3w2, lw1);

    const dim3 gg(4, M_PAD / 128);
    const dim3 hg(2, N_GRAPHS / 128);
    const dim3 agg_grid((N_NODES * 32 + 255) / 256, 2);

    // ---- layer 1 (fused agg + MLP-in) ----
    agg_mlp7<<<2048, 256>>>(x, c1w1, c1b1);
    gemm_h<false><<<gg, 256, GHSM_BYTES>>>(N_NODES, HID, p_mh, h_c1w2, c1b2, p_hh);

    // ---- layer 2 ----
    csr_aggh_chunk<<<agg_grid, 256>>>();
    gemm_h<false><<<gg, 256, GHSM_BYTES>>>(N_NODES, HID, p_th, h_c2w1, c2b1, p_mh);
    gemm_h<false><<<gg, 256, GHSM_BYTES>>>(N_NODES, HID, p_mh, h_c2w2, c2b2, p_hh);

    // ---- layer 3 ----
    csr_aggh_chunk<<<agg_grid, 256>>>();
    gemm_h<false><<<gg, 256, GHSM_BYTES>>>(N_NODES, HID, p_th, h_c3w1, c3b1, p_mh);
    gemm_h<false><<<gg, 256, GHSM_BYTES>>>(N_NODES, HID, p_mh, h_c3w2, c3b2, p_hh);

    // ---- mean pool ----
    pool_mean<<<N_GRAPHS, 128>>>();

    // ---- head ----
    gemm_h<true><<<hg, 256, GHSM_BYTES>>>(N_GRAPHS, 256, p_poolh, h_lw1, lb1, p_p1);
    head2<<<N_GRAPHS, 32>>>(lw2, lb2, out);
}

// round 16
// speedup vs baseline: 1.4895x; 1.4895x over previous
#include <cuda_runtime.h>
#include <cuda_fp16.h>
#include <cstdint>
#include <cstddef>

#define N_NODES 100000
#define N_EDGES 1600000
#define N_GRAPHS 4096
#define HID 512
#define M_PAD 100096            // 782 * 128
#define NCHUNK ((N_NODES + 1023) / 1024)

// ---------------- scratch (device globals; allocation-free) ----------------
__device__ uint16_t g_hh[(size_t)M_PAD * HID];   // node features (half)
__device__ uint16_t g_th[(size_t)M_PAD * HID];   // agg output (half)
__device__ uint16_t g_mh[(size_t)M_PAD * HID];   // MLP hidden (half)
__device__ uint16_t g_poolh[(size_t)N_GRAPHS * HID];
__device__ float    g_p1[(size_t)N_GRAPHS * 256];
__device__ uint16_t g_wh[5 * 512 * 512 + 256 * 512];  // [N,K] half weights
// CSR scratch
__device__ int g_deg[N_NODES];
__device__ int g_rows[N_NODES + 1];
__device__ int g_cur[N_NODES];
__device__ int g_csr[N_EDGES];
__device__ int g_gstart[N_GRAPHS + 1];
__device__ int g_bsum[NCHUNK];

__device__ __forceinline__ uint16_t f2h(float x) {
    return __half_as_ushort(__float2half_rn(x));
}

// ---------------- CSR build ----------------
__global__ void deg_count(const int* __restrict__ dst) {
    int e = blockIdx.x * blockDim.x + threadIdx.x;
    if (e < N_EDGES) atomicAdd(&g_deg[dst[e]], 1);
}

__global__ __launch_bounds__(1024) void scan1() {
    __shared__ int s[1024];
    const int b = blockIdx.x;
    const int tid = threadIdx.x;
    const int i = b * 1024 + tid;
    int v = (i < N_NODES) ? g_deg[i] : 0;
    s[tid] = v;
    __syncthreads();
#pragma unroll
    for (int off = 1; off < 1024; off <<= 1) {
        int t = (tid >= off) ? s[tid - off] : 0;
        __syncthreads();
        s[tid] += t;
        __syncthreads();
    }
    if (i < N_NODES) g_rows[i] = s[tid] - v;
    if (tid == 1023) g_bsum[b] = s[1023];
}

// scan3 with fused carry + fused graph_ranges (batch is sorted ascending)
__global__ __launch_bounds__(1024) void scan3(const int* __restrict__ batch) {
    __shared__ int carry;
    const int b = blockIdx.x;
    if (threadIdx.x == 0) {
        int c = 0;
        for (int i = 0; i < b; i++) c += g_bsum[i];
        carry = c;
        if (b == NCHUNK - 1) g_rows[N_NODES] = c + g_bsum[b];
    }
    __syncthreads();
    const int i = b * 1024 + threadIdx.x;
    if (i < N_NODES) {
        int r = g_rows[i] + carry;
        g_rows[i] = r;
        g_cur[i] = r;
    }
    // fused graph_ranges: global ids 0..N_GRAPHS do a lower_bound on batch
    if (i <= N_GRAPHS) {
        if (i == N_GRAPHS) {
            g_gstart[i] = N_NODES;
        } else {
            int lo = 0, hi = N_NODES;
            while (lo < hi) {
                int mid = (lo + hi) >> 1;
                if (batch[mid] < i) lo = mid + 1; else hi = mid;
            }
            g_gstart[i] = lo;
        }
    }
}

__global__ void csr_scatter(const int* __restrict__ src, const int* __restrict__ dst) {
    int e = blockIdx.x * blockDim.x + threadIdx.x;
    if (e >= N_EDGES) return;
    int pos = atomicAdd(&g_cur[dst[e]], 1);
    g_csr[pos] = src[e];
}

// ---------------- fused layer-1: agg7 + MLP-in ----------------
__global__ __launch_bounds__(256) void agg_mlp7(const float* __restrict__ x,
                                                const float* __restrict__ w,
                                                const float* __restrict__ bias) {
    __shared__ float sw[7 * 512];
    __shared__ float sb[512];
    for (int i = threadIdx.x; i < 7 * 512; i += 256) sw[i] = w[i];
    for (int i = threadIdx.x; i < 512; i += 256) sb[i] = bias[i];
    __syncthreads();

    const int lane = threadIdx.x & 31;
    const int wid = threadIdx.x >> 5;

    for (int node = blockIdx.x * 8 + wid; node < N_NODES; node += gridDim.x * 8) {
        int beg = g_rows[node], end = g_rows[node + 1];
        float a[7];
#pragma unroll
        for (int k = 0; k < 7; k++) a[k] = (lane == 0) ? x[(size_t)node * 7 + k] : 0.f;
        for (int e = beg + lane; e < end; e += 32) {
            int s = g_csr[e];
#pragma unroll
            for (int k = 0; k < 7; k++) a[k] += x[(size_t)s * 7 + k];
        }
#pragma unroll
        for (int off = 16; off; off >>= 1)
#pragma unroll
            for (int k = 0; k < 7; k++) a[k] += __shfl_xor_sync(0xFFFFFFFF, a[k], off);

        uint16_t* orow = g_mh + (size_t)node * 512;
#pragma unroll
        for (int jj = 0; jj < 16; jj++) {
            int j = jj * 32 + lane;
            float acc = sb[j];
#pragma unroll
            for (int k = 0; k < 7; k++) acc = fmaf(a[k], sw[k * 512 + j], acc);
            orow[j] = f2h(fmaxf(acc, 0.f));
        }
    }
}

// ---------------- L2-blocked aggregation (half in/out, fp32 sums) ----------------
// Plain write-back stores: g_th is producer->consumer (next GEMM reads it
// 4x through L2). Streaming hints here cost ~700us (R15 lesson).
__global__ __launch_bounds__(256) void csr_aggh_chunk() {
    int w = (int)(((long long)blockIdx.x * blockDim.x + threadIdx.x) >> 5);
    int lane = threadIdx.x & 31;
    if (w >= N_NODES) return;
    const int off = blockIdx.y * 256 + lane * 8;  // halves
    const int beg = g_rows[w], end = g_rows[w + 1];
    const uint16_t* base = g_hh + off;

    float acc[8];
    {
        uint4 s = *(const uint4*)(base + (size_t)w * HID);
        const __half2* p = (const __half2*)&s;
#pragma unroll
        for (int q = 0; q < 4; q++) {
            float2 f = __half22float2(p[q]);
            acc[q * 2] = f.x; acc[q * 2 + 1] = f.y;
        }
    }

    int e = beg;
    for (; e + 4 <= end; e += 4) {
        int s0 = g_csr[e], s1 = g_csr[e + 1], s2 = g_csr[e + 2], s3 = g_csr[e + 3];
        uint4 v0 = *(const uint4*)(base + (size_t)s0 * HID);
        uint4 v1 = *(const uint4*)(base + (size_t)s1 * HID);
        uint4 v2 = *(const uint4*)(base + (size_t)s2 * HID);
        uint4 v3 = *(const uint4*)(base + (size_t)s3 * HID);
        const __half2* p0 = (const __half2*)&v0;
        const __half2* p1 = (const __half2*)&v1;
        const __half2* p2 = (const __half2*)&v2;
        const __half2* p3 = (const __half2*)&v3;
#pragma unroll
        for (int q = 0; q < 4; q++) {
            float2 f0 = __half22float2(p0[q]);
            float2 f1 = __half22float2(p1[q]);
            float2 f2 = __half22float2(p2[q]);
            float2 f3 = __half22float2(p3[q]);
            acc[q * 2]     += (f0.x + f1.x) + (f2.x + f3.x);
            acc[q * 2 + 1] += (f0.y + f1.y) + (f2.y + f3.y);
        }
    }
    for (; e < end; e++) {
        uint4 v0 = *(const uint4*)(base + (size_t)g_csr[e] * HID);
        const __half2* p0 = (const __half2*)&v0;
#pragma unroll
        for (int q = 0; q < 4; q++) {
            float2 f0 = __half22float2(p0[q]);
            acc[q * 2] += f0.x;
            acc[q * 2 + 1] += f0.y;
        }
    }

    uint4 o;
    __half2* po = (__half2*)&o;
#pragma unroll
    for (int q = 0; q < 4; q++)
        po[q] = __floats2half2_rn(acc[q * 2], acc[q * 2 + 1]);
    *(uint4*)(g_th + (size_t)w * HID + off) = o;
}

// ---------------- all weight transposes fused: [K,N] fp32 -> [N,K] half ----------------
__global__ void w_to_half_all(const float* __restrict__ w0, const float* __restrict__ w1,
                              const float* __restrict__ w2, const float* __restrict__ w3,
                              const float* __restrict__ w4, const float* __restrict__ w5) {
    __shared__ float t[32][33];
    const int bx = blockIdx.x;
    const float* in;
    uint16_t* outp;
    int N, tile;
    if (bx < 1280) {
        int region = bx >> 8;
        tile = bx & 255;
        N = 512;
        switch (region) {
            case 0: in = w0; break;
            case 1: in = w1; break;
            case 2: in = w2; break;
            case 3: in = w3; break;
            default: in = w4; break;
        }
        outp = g_wh + (size_t)region * 262144;
    } else {
        tile = bx - 1280;
        N = 256;
        in = w5;
        outp = g_wh + (size_t)5 * 262144;
    }
    const int ntiles_n = N >> 5;
    const int n0 = (tile % ntiles_n) * 32;
    const int k0 = (tile / ntiles_n) * 32;
    const int K = 512;

    int tx = threadIdx.x, ty = threadIdx.y;  // (32,8)
#pragma unroll
    for (int i = 0; i < 4; i++)
        t[ty + i * 8][tx] = in[(size_t)(k0 + ty + i * 8) * N + n0 + tx];
    __syncthreads();
#pragma unroll
    for (int i = 0; i < 4; i++)
        outp[(size_t)(n0 + ty + i * 8) * K + k0 + tx] = f2h(t[tx][ty + i * 8]);
}

// ---------------- FP16 mma GEMM, 2-stage cp.async, 2 CTAs/SM (R12 best config) ----------------
#define STGH_BYTES 32768
#define GHSM_BYTES (2 * STGH_BYTES)

__device__ __forceinline__ void cp16(uint32_t dst, const void* src) {
    asm volatile("cp.async.cg.shared.global [%0], [%1], 16;" :: "r"(dst), "l"(src));
}

__device__ __forceinline__ void ldsm4(uint32_t* r, uint32_t a) {
    asm volatile("ldmatrix.sync.aligned.m8n8.x4.shared.b16 {%0,%1,%2,%3}, [%4];"
                 : "=r"(r[0]), "=r"(r[1]), "=r"(r[2]), "=r"(r[3]) : "r"(a));
}
__device__ __forceinline__ void ldsm2(uint32_t* r, uint32_t a) {
    asm volatile("ldmatrix.sync.aligned.m8n8.x2.shared.b16 {%0,%1}, [%2];"
                 : "=r"(r[0]), "=r"(r[1]) : "r"(a));
}

__device__ __forceinline__ void mma_h(float* d, const uint32_t* a, const uint32_t* b) {
    asm volatile(
        "mma.sync.aligned.m16n8k16.row.col.f32.f16.f16.f32 "
        "{%0,%1,%2,%3},{%4,%5,%6,%7},{%8,%9},{%0,%1,%2,%3};\n"
        : "+f"(d[0]), "+f"(d[1]), "+f"(d[2]), "+f"(d[3])
        : "r"(a[0]), "r"(a[1]), "r"(a[2]), "r"(a[3]), "r"(b[0]), "r"(b[1]));
}

// OUT_F32: store float2 to C (fp32, ldc); else half2 to C (half, ldc).
template <bool OUT_F32>
__global__ __launch_bounds__(256, 2) void gemm_h(
    int M, int ldc,
    const uint16_t* __restrict__ A, const uint16_t* __restrict__ B,
    const float* __restrict__ bias, void* __restrict__ Cv) {
    extern __shared__ __align__(128) char smc[];
    uint32_t smem_u32;
    asm("{ .reg .u64 t; cvta.to.shared.u64 t, %1; cvt.u32.u64 %0, t; }"
        : "=r"(smem_u32) : "l"(smc));

    const int tid = threadIdx.x;
    const int lane = tid & 31;
    const int warp = tid >> 5;
    const int wy = warp & 1;   // m 0/64
    const int wx = warp >> 1;  // n 0/32/64/96
    const int m0 = blockIdx.y * 128;
    const int n0 = blockIdx.x * 128;

    const int cr = tid >> 1;
    const int cb = (tid & 1) * 4;

    auto issue = [&](int ks) {
        uint32_t sa = smem_u32 + (uint32_t)(ks & 1) * STGH_BYTES;
        uint32_t sb = sa + 16384;
        const uint16_t* Ar = A + (size_t)(m0 + cr) * 512 + ks * 64;
        const uint16_t* Br = B + (size_t)(n0 + cr) * 512 + ks * 64;
#pragma unroll
        for (int q = 0; q < 4; q++) {
            int ch = cb + q;
            int sch = ch ^ (cr & 7);
            cp16(sa + (uint32_t)(cr * 128 + sch * 16), Ar + ch * 8);
            cp16(sb + (uint32_t)(cr * 128 + sch * 16), Br + ch * 8);
        }
        asm volatile("cp.async.commit_group;");
    };

    issue(0);

    float acc[4][4][4];
#pragma unroll
    for (int i = 0; i < 4; i++)
#pragma unroll
        for (int j = 0; j < 4; j++)
#pragma unroll
            for (int r = 0; r < 4; r++) acc[i][j][r] = 0.f;

    const int arow = lane & 15;
    const int asel = lane >> 4;
    const int brow = lane & 7;
    const int bsel = (lane >> 3) & 1;

    const int nks = 8;  // 512/64
    for (int ks = 0; ks < nks; ks++) {
        if (ks + 1 < nks) issue(ks + 1);
        else asm volatile("cp.async.commit_group;");
        asm volatile("cp.async.wait_group %0;" :: "n"(1));
        __syncthreads();

        uint32_t sa = smem_u32 + (uint32_t)(ks & 1) * STGH_BYTES;
        uint32_t sb = sa + 16384;
#pragma unroll
        for (int kk = 0; kk < 4; kk++) {
            uint32_t af[4][4], bf[4][2];
            const int ach = (2 * kk + asel) ^ (arow & 7);
            const int bch = (2 * kk + bsel) ^ brow;
#pragma unroll
            for (int i = 0; i < 4; i++)
                ldsm4(af[i], sa + (uint32_t)((wy * 64 + i * 16 + arow) * 128 + ach * 16));
#pragma unroll
            for (int j = 0; j < 4; j++)
                ldsm2(bf[j], sb + (uint32_t)((wx * 32 + j * 8 + brow) * 128 + bch * 16));
#pragma unroll
            for (int i = 0; i < 4; i++)
#pragma unroll
                for (int j = 0; j < 4; j++) mma_h(acc[i][j], af[i], bf[j]);
        }
        __syncthreads();
    }

    const int crow = lane >> 2;
    const int ccol = (lane & 3) << 1;
#pragma unroll
    for (int i = 0; i < 4; i++) {
        int r0 = m0 + wy * 64 + i * 16 + crow;
        int r1 = r0 + 8;
#pragma unroll
        for (int j = 0; j < 4; j++) {
            int c = n0 + wx * 32 + j * 8 + ccol;
            float b0 = bias[c], b1 = bias[c + 1];
            float v00 = fmaxf(acc[i][j][0] + b0, 0.f);
            float v01 = fmaxf(acc[i][j][1] + b1, 0.f);
            float v10 = fmaxf(acc[i][j][2] + b0, 0.f);
            float v11 = fmaxf(acc[i][j][3] + b1, 0.f);
            if (OUT_F32) {
                float* C = (float*)Cv;
                if (r0 < M) { float2 v = {v00, v01}; *(float2*)&C[(size_t)r0 * ldc + c] = v; }
                if (r1 < M) { float2 v = {v10, v11}; *(float2*)&C[(size_t)r1 * ldc + c] = v; }
            } else {
                uint16_t* C = (uint16_t*)Cv;
                if (r0 < M) {
                    __half2 v = __floats2half2_rn(v00, v01);
                    *(uint32_t*)&C[(size_t)r0 * ldc + c] = *(uint32_t*)&v;
                }
                if (r1 < M) {
                    __half2 v = __floats2half2_rn(v10, v11);
                    *(uint32_t*)&C[(size_t)r1 * ldc + c] = *(uint32_t*)&v;
                }
            }
        }
    }
}

// ---------------- pooling + head ----------------
__global__ __launch_bounds__(128) void pool_mean() {
    int g = blockIdx.x;
    int beg = g_gstart[g], end = g_gstart[g + 1];
    const int t = threadIdx.x;  // 4 halves each
    float a0 = 0.f, a1 = 0.f, a2 = 0.f, a3 = 0.f;
    for (int n = beg; n < end; n++) {
        uint2 v = *(const uint2*)(g_hh + (size_t)n * HID + t * 4);
        float2 f0 = __half22float2(*(__half2*)&v.x);
        float2 f1 = __half22float2(*(__half2*)&v.y);
        a0 += f0.x; a1 += f0.y; a2 += f1.x; a3 += f1.y;
    }
    float c = fmaxf((float)(end - beg), 1.f);
    uint2 o;
    __half2 o0 = __floats2half2_rn(a0 / c, a1 / c);
    __half2 o1 = __floats2half2_rn(a2 / c, a3 / c);
    o.x = *(uint32_t*)&o0; o.y = *(uint32_t*)&o1;
    *(uint2*)(g_poolh + (size_t)g * HID + t * 4) = o;
}

__global__ void head2(const float* __restrict__ w, const float* __restrict__ b,
                      float* __restrict__ out) {
    int g = blockIdx.x;
    int o = threadIdx.x;
    if (o >= 12) return;
    float acc = b[o];
    const float* row = g_p1 + (size_t)g * 256;
#pragma unroll 8
    for (int k = 0; k < 256; k++) acc = fmaf(row[k], w[k * 12 + o], acc);
    out[(size_t)g * 12 + o] = acc;
}

// ---------------- launch ----------------
extern "C" void kernel_launch(void* const* d_in, const int* in_sizes, int n_in,
                              void* d_out, int out_size) {
    const float* x = (const float*)d_in[0];
    const int* ei = (const int*)d_in[1];
    const int* src = ei;
    const int* dst = ei + N_EDGES;
    const int* batch = (const int*)d_in[2];
    const float* c1w1 = (const float*)d_in[3];
    const float* c1b1 = (const float*)d_in[4];
    const float* c1w2 = (const float*)d_in[5];
    const float* c1b2 = (const float*)d_in[6];
    const float* c2w1 = (const float*)d_in[7];
    const float* c2b1 = (const float*)d_in[8];
    const float* c2w2 = (const float*)d_in[9];
    const float* c2b2 = (const float*)d_in[10];
    const float* c3w1 = (const float*)d_in[11];
    const float* c3b1 = (const float*)d_in[12];
    const float* c3w2 = (const float*)d_in[13];
    const float* c3b2 = (const float*)d_in[14];
    const float* lw1 = (const float*)d_in[15];
    const float* lb1 = (const float*)d_in[16];
    const float* lw2 = (const float*)d_in[17];
    const float* lb2 = (const float*)d_in[18];
    float* out = (float*)d_out;

    uint16_t *p_hh, *p_th, *p_mh, *p_poolh, *p_wh;
    float *p_p1;
    int *p_deg;
    cudaGetSymbolAddress((void**)&p_hh, g_hh);
    cudaGetSymbolAddress((void**)&p_th, g_th);
    cudaGetSymbolAddress((void**)&p_mh, g_mh);
    cudaGetSymbolAddress((void**)&p_poolh, g_poolh);
    cudaGetSymbolAddress((void**)&p_wh, g_wh);
    cudaGetSymbolAddress((void**)&p_p1, g_p1);
    cudaGetSymbolAddress((void**)&p_deg, g_deg);

    uint16_t* h_c1w2 = p_wh + 0 * 262144;
    uint16_t* h_c2w1 = p_wh + 1 * 262144;
    uint16_t* h_c2w2 = p_wh + 2 * 262144;
    uint16_t* h_c3w1 = p_wh + 3 * 262144;
    uint16_t* h_c3w2 = p_wh + 4 * 262144;
    uint16_t* h_lw1  = p_wh + 5 * 262144;

    cudaFuncSetAttribute(gemm_h<true>, cudaFuncAttributeMaxDynamicSharedMemorySize, GHSM_BYTES);
    cudaFuncSetAttribute(gemm_h<false>, cudaFuncAttributeMaxDynamicSharedMemorySize, GHSM_BYTES);

    // ---- CSR build + graph ranges + weight prep ----
    cudaMemsetAsync(p_deg, 0, N_NODES * sizeof(int));
    deg_count<<<(N_EDGES + 255) / 256, 256>>>(dst);
    scan1<<<NCHUNK, 1024>>>();
    scan3<<<NCHUNK, 1024>>>(batch);
    csr_scatter<<<(N_EDGES + 255) / 256, 256>>>(src, dst);
    w_to_half_all<<<1408, dim3(32, 8)>>>(c1w2, c2w1, c2w2, c3w1, c3w2, lw1);

    const dim3 gg(4, M_PAD / 128);
    const dim3 hg(2, N_GRAPHS / 128);
    const dim3 agg_grid((N_NODES * 32 + 255) / 256, 2);

    // ---- layer 1 (fused agg + MLP-in) ----
    agg_mlp7<<<2048, 256>>>(x, c1w1, c1b1);
    gemm_h<false><<<gg, 256, GHSM_BYTES>>>(N_NODES, HID, p_mh, h_c1w2, c1b2, p_hh);

    // ---- layer 2 ----
    csr_aggh_chunk<<<agg_grid, 256>>>();
    gemm_h<false><<<gg, 256, GHSM_BYTES>>>(N_NODES, HID, p_th, h_c2w1, c2b1, p_mh);
    gemm_h<false><<<gg, 256, GHSM_BYTES>>>(N_NODES, HID, p_mh, h_c2w2, c2b2, p_hh);

    // ---- layer 3 ----
    csr_aggh_chunk<<<agg_grid, 256>>>();
    gemm_h<false><<<gg, 256, GHSM_BYTES>>>(N_NODES, HID, p_th, h_c3w1, c3b1, p_mh);
    gemm_h<false><<<gg, 256, GHSM_BYTES>>>(N_NODES, HID, p_mh, h_c3w2, c3b2, p_hh);

    // ---- mean pool ----
    pool_mean<<<N_GRAPHS, 128>>>();

    // ---- head ----
    gemm_h<true><<<hg, 256, GHSM_BYTES>>>(N_GRAPHS, 256, p_poolh, h_lw1, lb1, p_p1);
    head2<<<N_GRAPHS, 32>>>(lw2, lb2, out);
}

// round 17
// speedup vs baseline: 1.5138x; 1.0163x over previous
#include <cuda_runtime.h>
#include <cuda_fp16.h>
#include <cstdint>
#include <cstddef>

#define N_NODES 100000
#define N_EDGES 1600000
#define N_GRAPHS 4096
#define HID 512
#define M_PAD 100096            // 782 * 128
#define NCHUNK ((N_NODES + 1023) / 1024)

// ---------------- scratch (device globals; allocation-free) ----------------
__device__ uint16_t g_hh[(size_t)M_PAD * HID];   // node features (half)
__device__ uint16_t g_th[(size_t)M_PAD * HID];   // agg output (half)
__device__ uint16_t g_mh[(size_t)M_PAD * HID];   // MLP hidden (half)
__device__ uint16_t g_poolh[(size_t)N_GRAPHS * HID];
__device__ float    g_pools[(size_t)N_GRAPHS * HID];  // fp32 pool sums (zero at entry, re-zeroed by pool_div)
__device__ float    g_p1[(size_t)N_GRAPHS * 256];
__device__ uint16_t g_wh[5 * 512 * 512 + 256 * 512];  // [N,K] half weights
// CSR scratch
__device__ int g_deg[N_NODES];
__device__ int g_rows[N_NODES + 1];
__device__ int g_cur[N_NODES];
__device__ int g_csr[N_EDGES];
__device__ int g_gstart[N_GRAPHS + 1];
__device__ int g_bsum[NCHUNK];

__device__ __forceinline__ uint16_t f2h(float x) {
    return __half_as_ushort(__float2half_rn(x));
}

// ---------------- CSR build ----------------
__global__ void deg_count(const int* __restrict__ dst) {
    int e = blockIdx.x * blockDim.x + threadIdx.x;
    if (e < N_EDGES) atomicAdd(&g_deg[dst[e]], 1);
}

__global__ __launch_bounds__(1024) void scan1() {
    __shared__ int s[1024];
    const int b = blockIdx.x;
    const int tid = threadIdx.x;
    const int i = b * 1024 + tid;
    int v = (i < N_NODES) ? g_deg[i] : 0;
    s[tid] = v;
    __syncthreads();
#pragma unroll
    for (int off = 1; off < 1024; off <<= 1) {
        int t = (tid >= off) ? s[tid - off] : 0;
        __syncthreads();
        s[tid] += t;
        __syncthreads();
    }
    if (i < N_NODES) g_rows[i] = s[tid] - v;
    if (tid == 1023) g_bsum[b] = s[1023];
}

// scan3 with fused carry + fused graph_ranges (batch is sorted ascending)
__global__ __launch_bounds__(1024) void scan3(const int* __restrict__ batch) {
    __shared__ int carry;
    const int b = blockIdx.x;
    if (threadIdx.x == 0) {
        int c = 0;
        for (int i = 0; i < b; i++) c += g_bsum[i];
        carry = c;
        if (b == NCHUNK - 1) g_rows[N_NODES] = c + g_bsum[b];
    }
    __syncthreads();
    const int i = b * 1024 + threadIdx.x;
    if (i < N_NODES) {
        int r = g_rows[i] + carry;
        g_rows[i] = r;
        g_cur[i] = r;
    }
    if (i <= N_GRAPHS) {
        if (i == N_GRAPHS) {
            g_gstart[i] = N_NODES;
        } else {
            int lo = 0, hi = N_NODES;
            while (lo < hi) {
                int mid = (lo + hi) >> 1;
                if (batch[mid] < i) lo = mid + 1; else hi = mid;
            }
            g_gstart[i] = lo;
        }
    }
}

__global__ void csr_scatter(const int* __restrict__ src, const int* __restrict__ dst) {
    int e = blockIdx.x * blockDim.x + threadIdx.x;
    if (e >= N_EDGES) return;
    int pos = atomicAdd(&g_cur[dst[e]], 1);
    g_csr[pos] = src[e];
}

// ---------------- fused layer-1: agg7 + MLP-in ----------------
__global__ __launch_bounds__(256) void agg_mlp7(const float* __restrict__ x,
                                                const float* __restrict__ w,
                                                const float* __restrict__ bias) {
    __shared__ float sw[7 * 512];
    __shared__ float sb[512];
    for (int i = threadIdx.x; i < 7 * 512; i += 256) sw[i] = w[i];
    for (int i = threadIdx.x; i < 512; i += 256) sb[i] = bias[i];
    __syncthreads();

    const int lane = threadIdx.x & 31;
    const int wid = threadIdx.x >> 5;

    for (int node = blockIdx.x * 8 + wid; node < N_NODES; node += gridDim.x * 8) {
        int beg = g_rows[node], end = g_rows[node + 1];
        float a[7];
#pragma unroll
        for (int k = 0; k < 7; k++) a[k] = (lane == 0) ? x[(size_t)node * 7 + k] : 0.f;
        for (int e = beg + lane; e < end; e += 32) {
            int s = g_csr[e];
#pragma unroll
            for (int k = 0; k < 7; k++) a[k] += x[(size_t)s * 7 + k];
        }
#pragma unroll
        for (int off = 16; off; off >>= 1)
#pragma unroll
            for (int k = 0; k < 7; k++) a[k] += __shfl_xor_sync(0xFFFFFFFF, a[k], off);

        uint16_t* orow = g_mh + (size_t)node * 512;
#pragma unroll
        for (int jj = 0; jj < 16; jj++) {
            int j = jj * 32 + lane;
            float acc = sb[j];
#pragma unroll
            for (int k = 0; k < 7; k++) acc = fmaf(a[k], sw[k * 512 + j], acc);
            orow[j] = f2h(fmaxf(acc, 0.f));
        }
    }
}

// ---------------- L2-blocked aggregation (half in/out, fp32 sums) ----------------
__global__ __launch_bounds__(256) void csr_aggh_chunk() {
    int w = (int)(((long long)blockIdx.x * blockDim.x + threadIdx.x) >> 5);
    int lane = threadIdx.x & 31;
    if (w >= N_NODES) return;
    const int off = blockIdx.y * 256 + lane * 8;  // halves
    const int beg = g_rows[w], end = g_rows[w + 1];
    const uint16_t* base = g_hh + off;

    float acc[8];
    {
        uint4 s = *(const uint4*)(base + (size_t)w * HID);
        const __half2* p = (const __half2*)&s;
#pragma unroll
        for (int q = 0; q < 4; q++) {
            float2 f = __half22float2(p[q]);
            acc[q * 2] = f.x; acc[q * 2 + 1] = f.y;
        }
    }

    int e = beg;
    for (; e + 4 <= end; e += 4) {
        int s0 = g_csr[e], s1 = g_csr[e + 1], s2 = g_csr[e + 2], s3 = g_csr[e + 3];
        uint4 v0 = *(const uint4*)(base + (size_t)s0 * HID);
        uint4 v1 = *(const uint4*)(base + (size_t)s1 * HID);
        uint4 v2 = *(const uint4*)(base + (size_t)s2 * HID);
        uint4 v3 = *(const uint4*)(base + (size_t)s3 * HID);
        const __half2* p0 = (const __half2*)&v0;
        const __half2* p1 = (const __half2*)&v1;
        const __half2* p2 = (const __half2*)&v2;
        const __half2* p3 = (const __half2*)&v3;
#pragma unroll
        for (int q = 0; q < 4; q++) {
            float2 f0 = __half22float2(p0[q]);
            float2 f1 = __half22float2(p1[q]);
            float2 f2 = __half22float2(p2[q]);
            float2 f3 = __half22float2(p3[q]);
            acc[q * 2]     += (f0.x + f1.x) + (f2.x + f3.x);
            acc[q * 2 + 1] += (f0.y + f1.y) + (f2.y + f3.y);
        }
    }
    for (; e < end; e++) {
        uint4 v0 = *(const uint4*)(base + (size_t)g_csr[e] * HID);
        const __half2* p0 = (const __half2*)&v0;
#pragma unroll
        for (int q = 0; q < 4; q++) {
            float2 f0 = __half22float2(p0[q]);
            acc[q * 2] += f0.x;
            acc[q * 2 + 1] += f0.y;
        }
    }

    uint4 o;
    __half2* po = (__half2*)&o;
#pragma unroll
    for (int q = 0; q < 4; q++)
        po[q] = __floats2half2_rn(acc[q * 2], acc[q * 2 + 1]);
    *(uint4*)(g_th + (size_t)w * HID + off) = o;
}

// ---------------- all weight transposes fused: [K,N] fp32 -> [N,K] half ----------------
__global__ void w_to_half_all(const float* __restrict__ w0, const float* __restrict__ w1,
                              const float* __restrict__ w2, const float* __restrict__ w3,
                              const float* __restrict__ w4, const float* __restrict__ w5) {
    __shared__ float t[32][33];
    const int bx = blockIdx.x;
    const float* in;
    uint16_t* outp;
    int N, tile;
    if (bx < 1280) {
        int region = bx >> 8;
        tile = bx & 255;
        N = 512;
        switch (region) {
            case 0: in = w0; break;
            case 1: in = w1; break;
            case 2: in = w2; break;
            case 3: in = w3; break;
            default: in = w4; break;
        }
        outp = g_wh + (size_t)region * 262144;
    } else {
        tile = bx - 1280;
        N = 256;
        in = w5;
        outp = g_wh + (size_t)5 * 262144;
    }
    const int ntiles_n = N >> 5;
    const int n0 = (tile % ntiles_n) * 32;
    const int k0 = (tile / ntiles_n) * 32;
    const int K = 512;

    int tx = threadIdx.x, ty = threadIdx.y;  // (32,8)
#pragma unroll
    for (int i = 0; i < 4; i++)
        t[ty + i * 8][tx] = in[(size_t)(k0 + ty + i * 8) * N + n0 + tx];
    __syncthreads();
#pragma unroll
    for (int i = 0; i < 4; i++)
        outp[(size_t)(n0 + ty + i * 8) * K + k0 + tx] = f2h(t[tx][ty + i * 8]);
}

// ---------------- FP16 mma GEMM, 2-stage cp.async, 2 CTAs/SM ----------------
// MODE 0: C = half[ldc]; MODE 1: C = float[ldc]; MODE 2: pooled (no C store,
// segmented per-graph column sums -> atomicAdd into g_pools).
#define STGH_BYTES 32768
#define GHSM_BYTES (2 * STGH_BYTES)
#define POOL_TILE_STRIDE 132
#define GHSM_POOL (128 * POOL_TILE_STRIDE * 4)   // 67584 >= 65536 stages

__device__ __forceinline__ void cp16(uint32_t dst, const void* src) {
    asm volatile("cp.async.cg.shared.global [%0], [%1], 16;" :: "r"(dst), "l"(src));
}

__device__ __forceinline__ void ldsm4(uint32_t* r, uint32_t a) {
    asm volatile("ldmatrix.sync.aligned.m8n8.x4.shared.b16 {%0,%1,%2,%3}, [%4];"
                 : "=r"(r[0]), "=r"(r[1]), "=r"(r[2]), "=r"(r[3]) : "r"(a));
}
__device__ __forceinline__ void ldsm2(uint32_t* r, uint32_t a) {
    asm volatile("ldmatrix.sync.aligned.m8n8.x2.shared.b16 {%0,%1}, [%2];"
                 : "=r"(r[0]), "=r"(r[1]) : "r"(a));
}

__device__ __forceinline__ void mma_h(float* d, const uint32_t* a, const uint32_t* b) {
    asm volatile(
        "mma.sync.aligned.m16n8k16.row.col.f32.f16.f16.f32 "
        "{%0,%1,%2,%3},{%4,%5,%6,%7},{%8,%9},{%0,%1,%2,%3};\n"
        : "+f"(d[0]), "+f"(d[1]), "+f"(d[2]), "+f"(d[3])
        : "r"(a[0]), "r"(a[1]), "r"(a[2]), "r"(a[3]), "r"(b[0]), "r"(b[1]));
}

template <int MODE>
__global__ __launch_bounds__(256, 2) void gemm_h(
    int M, int ldc,
    const uint16_t* __restrict__ A, const uint16_t* __restrict__ B,
    const float* __restrict__ bias, void* __restrict__ Cv,
    const int* __restrict__ batch, float* __restrict__ pools) {
    extern __shared__ __align__(128) char smc[];
    uint32_t smem_u32;
    asm("{ .reg .u64 t; cvta.to.shared.u64 t, %1; cvt.u32.u64 %0, t; }"
        : "=r"(smem_u32) : "l"(smc));

    const int tid = threadIdx.x;
    const int lane = tid & 31;
    const int warp = tid >> 5;
    const int wy = warp & 1;   // m 0/64
    const int wx = warp >> 1;  // n 0/32/64/96
    const int m0 = blockIdx.y * 128;
    const int n0 = blockIdx.x * 128;

    const int cr = tid >> 1;
    const int cb = (tid & 1) * 4;

    auto issue = [&](int ks) {
        uint32_t sa = smem_u32 + (uint32_t)(ks & 1) * STGH_BYTES;
        uint32_t sb = sa + 16384;
        const uint16_t* Ar = A + (size_t)(m0 + cr) * 512 + ks * 64;
        const uint16_t* Br = B + (size_t)(n0 + cr) * 512 + ks * 64;
#pragma unroll
        for (int q = 0; q < 4; q++) {
            int ch = cb + q;
            int sch = ch ^ (cr & 7);
            cp16(sa + (uint32_t)(cr * 128 + sch * 16), Ar + ch * 8);
            cp16(sb + (uint32_t)(cr * 128 + sch * 16), Br + ch * 8);
        }
        asm volatile("cp.async.commit_group;");
    };

    issue(0);

    float acc[4][4][4];
#pragma unroll
    for (int i = 0; i < 4; i++)
#pragma unroll
        for (int j = 0; j < 4; j++)
#pragma unroll
            for (int r = 0; r < 4; r++) acc[i][j][r] = 0.f;

    const int arow = lane & 15;
    const int asel = lane >> 4;
    const int brow = lane & 7;
    const int bsel = (lane >> 3) & 1;

    const int nks = 8;  // 512/64
    for (int ks = 0; ks < nks; ks++) {
        if (ks + 1 < nks) issue(ks + 1);
        else asm volatile("cp.async.commit_group;");
        asm volatile("cp.async.wait_group %0;" :: "n"(1));
        __syncthreads();

        uint32_t sa = smem_u32 + (uint32_t)(ks & 1) * STGH_BYTES;
        uint32_t sb = sa + 16384;
#pragma unroll
        for (int kk = 0; kk < 4; kk++) {
            uint32_t af[4][4], bf[4][2];
            const int ach = (2 * kk + asel) ^ (arow & 7);
            const int bch = (2 * kk + bsel) ^ brow;
#pragma unroll
            for (int i = 0; i < 4; i++)
                ldsm4(af[i], sa + (uint32_t)((wy * 64 + i * 16 + arow) * 128 + ach * 16));
#pragma unroll
            for (int j = 0; j < 4; j++)
                ldsm2(bf[j], sb + (uint32_t)((wx * 32 + j * 8 + brow) * 128 + bch * 16));
#pragma unroll
            for (int i = 0; i < 4; i++)
#pragma unroll
                for (int j = 0; j < 4; j++) mma_h(acc[i][j], af[i], bf[j]);
        }
        __syncthreads();
    }

    const int crow = lane >> 2;
    const int ccol = (lane & 3) << 1;

    if (MODE == 2) {
        // ---- pooled epilogue: relu tile -> smem -> segmented per-graph sums ----
        float* tile = (float*)smc;  // 128 x POOL_TILE_STRIDE
        __shared__ int sbat[128];
#pragma unroll
        for (int i = 0; i < 4; i++) {
            int r0l = wy * 64 + i * 16 + crow;
            int r1l = r0l + 8;
#pragma unroll
            for (int j = 0; j < 4; j++) {
                int cl = wx * 32 + j * 8 + ccol;
                float b0 = bias[n0 + cl], b1 = bias[n0 + cl + 1];
                tile[r0l * POOL_TILE_STRIDE + cl]     = fmaxf(acc[i][j][0] + b0, 0.f);
                tile[r0l * POOL_TILE_STRIDE + cl + 1] = fmaxf(acc[i][j][1] + b1, 0.f);
                tile[r1l * POOL_TILE_STRIDE + cl]     = fmaxf(acc[i][j][2] + b0, 0.f);
                tile[r1l * POOL_TILE_STRIDE + cl + 1] = fmaxf(acc[i][j][3] + b1, 0.f);
            }
        }
        if (tid < 128) {
            int r = m0 + tid;
            sbat[tid] = (r < M) ? batch[r] : -1;
        }
        __syncthreads();

        const int col = tid & 127;
        const int half = tid >> 7;       // 0..1
        const int rbeg = half * 64, rend = rbeg + 64;
        float s = 0.f;
        int cur = sbat[rbeg];
        for (int r = rbeg; r < rend; r++) {
            int b = sbat[r];
            if (b != cur) {
                if (cur >= 0) atomicAdd(&pools[(size_t)cur * HID + n0 + col], s);
                s = 0.f;
                cur = b;
            }
            s += tile[r * POOL_TILE_STRIDE + col];
        }
        if (cur >= 0) atomicAdd(&pools[(size_t)cur * HID + n0 + col], s);
    } else {
#pragma unroll
        for (int i = 0; i < 4; i++) {
            int r0 = m0 + wy * 64 + i * 16 + crow;
            int r1 = r0 + 8;
#pragma unroll
            for (int j = 0; j < 4; j++) {
                int c = n0 + wx * 32 + j * 8 + ccol;
                float b0 = bias[c], b1 = bias[c + 1];
                float v00 = fmaxf(acc[i][j][0] + b0, 0.f);
                float v01 = fmaxf(acc[i][j][1] + b1, 0.f);
                float v10 = fmaxf(acc[i][j][2] + b0, 0.f);
                float v11 = fmaxf(acc[i][j][3] + b1, 0.f);
                if (MODE == 1) {
                    float* C = (float*)Cv;
                    if (r0 < M) { float2 v = {v00, v01}; *(float2*)&C[(size_t)r0 * ldc + c] = v; }
                    if (r1 < M) { float2 v = {v10, v11}; *(float2*)&C[(size_t)r1 * ldc + c] = v; }
                } else {
                    uint16_t* C = (uint16_t*)Cv;
                    if (r0 < M) {
                        __half2 v = __floats2half2_rn(v00, v01);
                        *(uint32_t*)&C[(size_t)r0 * ldc + c] = *(uint32_t*)&v;
                    }
                    if (r1 < M) {
                        __half2 v = __floats2half2_rn(v10, v11);
                        *(uint32_t*)&C[(size_t)r1 * ldc + c] = *(uint32_t*)&v;
                    }
                }
            }
        }
    }
}

// ---------------- pool finalize: half(pools/cnt), re-zero pools ----------------
__global__ __launch_bounds__(128) void pool_div() {
    int g = blockIdx.x;
    float cnt = fmaxf((float)(g_gstart[g + 1] - g_gstart[g]), 1.f);
    float inv = 1.f / cnt;
#pragma unroll
    for (int q = 0; q < 4; q++) {
        int c = q * 128 + threadIdx.x;
        size_t idx = (size_t)g * HID + c;
        g_poolh[idx] = f2h(g_pools[idx] * inv);
        g_pools[idx] = 0.f;  // restore invariant for next call
    }
}

__global__ void head2(const float* __restrict__ w, const float* __restrict__ b,
                      float* __restrict__ out) {
    int g = blockIdx.x;
    int o = threadIdx.x;
    if (o >= 12) return;
    float acc = b[o];
    const float* row = g_p1 + (size_t)g * 256;
#pragma unroll 8
    for (int k = 0; k < 256; k++) acc = fmaf(row[k], w[k * 12 + o], acc);
    out[(size_t)g * 12 + o] = acc;
}

// ---------------- launch ----------------
extern "C" void kernel_launch(void* const* d_in, const int* in_sizes, int n_in,
                              void* d_out, int out_size) {
    const float* x = (const float*)d_in[0];
    const int* ei = (const int*)d_in[1];
    const int* src = ei;
    const int* dst = ei + N_EDGES;
    const int* batch = (const int*)d_in[2];
    const float* c1w1 = (const float*)d_in[3];
    const float* c1b1 = (const float*)d_in[4];
    const float* c1w2 = (const float*)d_in[5];
    const float* c1b2 = (const float*)d_in[6];
    const float* c2w1 = (const float*)d_in[7];
    const float* c2b1 = (const float*)d_in[8];
    const float* c2w2 = (const float*)d_in[9];
    const float* c2b2 = (const float*)d_in[10];
    const float* c3w1 = (const float*)d_in[11];
    const float* c3b1 = (const float*)d_in[12];
    const float* c3w2 = (const float*)d_in[13];
    const float* c3b2 = (const float*)d_in[14];
    const float* lw1 = (const float*)d_in[15];
    const float* lb1 = (const float*)d_in[16];
    const float* lw2 = (const float*)d_in[17];
    const float* lb2 = (const float*)d_in[18];
    float* out = (float*)d_out;

    uint16_t *p_hh, *p_th, *p_mh, *p_poolh, *p_wh;
    float *p_p1, *p_pools;
    int *p_deg;
    cudaGetSymbolAddress((void**)&p_hh, g_hh);
    cudaGetSymbolAddress((void**)&p_th, g_th);
    cudaGetSymbolAddress((void**)&p_mh, g_mh);
    cudaGetSymbolAddress((void**)&p_poolh, g_poolh);
    cudaGetSymbolAddress((void**)&p_wh, g_wh);
    cudaGetSymbolAddress((void**)&p_p1, g_p1);
    cudaGetSymbolAddress((void**)&p_pools, g_pools);
    cudaGetSymbolAddress((void**)&p_deg, g_deg);

    uint16_t* h_c1w2 = p_wh + 0 * 262144;
    uint16_t* h_c2w1 = p_wh + 1 * 262144;
    uint16_t* h_c2w2 = p_wh + 2 * 262144;
    uint16_t* h_c3w1 = p_wh + 3 * 262144;
    uint16_t* h_c3w2 = p_wh + 4 * 262144;
    uint16_t* h_lw1  = p_wh + 5 * 262144;

    cudaFuncSetAttribute(gemm_h<0>, cudaFuncAttributeMaxDynamicSharedMemorySize, GHSM_BYTES);
    cudaFuncSetAttribute(gemm_h<1>, cudaFuncAttributeMaxDynamicSharedMemorySize, GHSM_BYTES);
    cudaFuncSetAttribute(gemm_h<2>, cudaFuncAttributeMaxDynamicSharedMemorySize, GHSM_POOL);

    // ---- CSR build + graph ranges + weight prep ----
    cudaMemsetAsync(p_deg, 0, N_NODES * sizeof(int));
    deg_count<<<(N_EDGES + 255) / 256, 256>>>(dst);
    scan1<<<NCHUNK, 1024>>>();
    scan3<<<NCHUNK, 1024>>>(batch);
    csr_scatter<<<(N_EDGES + 255) / 256, 256>>>(src, dst);
    w_to_half_all<<<1408, dim3(32, 8)>>>(c1w2, c2w1, c2w2, c3w1, c3w2, lw1);

    const dim3 gg(4, M_PAD / 128);
    const dim3 hg(2, N_GRAPHS / 128);
    const dim3 agg_grid((N_NODES * 32 + 255) / 256, 2);

    // ---- layer 1 (fused agg + MLP-in) ----
    agg_mlp7<<<2048, 256>>>(x, c1w1, c1b1);
    gemm_h<0><<<gg, 256, GHSM_BYTES>>>(N_NODES, HID, p_mh, h_c1w2, c1b2, p_hh, nullptr, nullptr);

    // ---- layer 2 ----
    csr_aggh_chunk<<<agg_grid, 256>>>();
    gemm_h<0><<<gg, 256, GHSM_BYTES>>>(N_NODES, HID, p_th, h_c2w1, c2b1, p_mh, nullptr, nullptr);
    gemm_h<0><<<gg, 256, GHSM_BYTES>>>(N_NODES, HID, p_mh, h_c2w2, c2b2, p_hh, nullptr, nullptr);

    // ---- layer 3 (second GEMM fuses mean-pool; no C store) ----
    csr_aggh_chunk<<<agg_grid, 256>>>();
    gemm_h<0><<<gg, 256, GHSM_BYTES>>>(N_NODES, HID, p_th, h_c3w1, c3b1, p_mh, nullptr, nullptr);
    gemm_h<2><<<gg, 256, GHSM_POOL>>>(N_NODES, HID, p_mh, h_c3w2, c3b2, nullptr, batch, p_pools);

    // ---- pool finalize ----
    pool_div<<<N_GRAPHS, 128>>>();

    // ---- head ----
    gemm_h<1><<<hg, 256, GHSM_BYTES>>>(N_GRAPHS, 256, p_poolh, h_lw1, lb1, p_p1, nullptr, nullptr);
    head2<<<N_GRAPHS, 32>>>(lw2, lb2, out);
}